// round 15
// baseline (speedup 1.0000x reference)
#include <cuda_runtime.h>
#include <cstdint>

// CostBuilder: stereo cost-volume construction.
// left, right: (B=4, C=32, H=64, W=128) fp32
// out:         (B, 2C=64, D=48, H, W) fp32
//   out[b, c,   d, h, w] = (w>=d) ? left [b,c,h,w]   : 0
//   out[b, C+c, d, h, w] = (w>=d) ? right[b,c,h,w-d] : 0
//
// R15: R13 (specialized left path, best: 73.6% DRAM) + R14's compile-time
// sub-shift decomposition, implemented with ALIGNED vector LDS instead of
// shuffles. DPB=4 => float4-shift k=d>>2=dg is block-uniform; per pass the
// right path does 2 independent LDS.128 (A=s4[lane-k], B=s4[lane-k-1]) and
// assembles all 4 sub-shift variants by compile-time component selection.
// No swizzle ALU, no shuffle serialization, 2 LDS.128 per 4 STG.128.

namespace {
constexpr int B   = 4;
constexpr int C   = 32;
constexpr int H   = 64;
constexpr int W   = 128;
constexpr int D   = 48;              // MAX_DISP / 4
constexpr int HW  = H * W;           // 8192
constexpr int TPB = 256;
constexpr int DPB = 4;               // d values per block (aligned group)
constexpr int NDG = D / DPB;         // 12 d-groups
constexpr int PASSES = HW / 4 / TPB; // 8 float4 passes per plane
}

__global__ __launch_bounds__(TPB) void cost_builder_kernel(
    const float* __restrict__ left,
    const float* __restrict__ right,
    float* __restrict__ out)
{
    const int g    = blockIdx.x;
    const int dg   = g % NDG;            // d-group 0..11  (d = 4*dg + dd)
    const int bc2  = g / NDG;            // output channel-plane 0..255
    const int b    = bc2 >> 6;
    const int ch   = bc2 & 63;
    const bool is_right = ch >= C;
    const int c    = ch & (C - 1);

    const float* src = (is_right ? right : left) + (size_t)(b * C + c) * HW;
    const float4* src4 = reinterpret_cast<const float4*>(src);

    __shared__ float4 s4[HW / 4];        // 32KB plane as float4s (right path)

    const int tid  = threadIdx.x;
    const int lane = tid & 31;
    const int w    = lane << 2;          // this lane's w within its row
    const int d0   = dg * DPB;

    const unsigned outbase0 = (unsigned)bc2 * D * HW;
    float4* outp[DPB];
    #pragma unroll
    for (int dd = 0; dd < DPB; ++dd)
        outp[dd] = reinterpret_cast<float4*>(out + outbase0 + (unsigned)(d0 + dd) * HW);

    if (!is_right) {
        // ---- LEFT PATH: d-invariant data, registers only, no smem/sync ----
        #pragma unroll
        for (int p = 0; p < PASSES; ++p) {
            const int i = p * TPB + tid;
            const float4 lv = src4[i];
            #pragma unroll
            for (int dd = 0; dd < DPB; ++dd) {
                const int d = d0 + dd;
                float4 v;
                v.x = (w     >= d) ? lv.x : 0.0f;
                v.y = (w + 1 >= d) ? lv.y : 0.0f;
                v.z = (w + 2 >= d) ? lv.z : 0.0f;
                v.w = (w + 3 >= d) ? lv.w : 0.0f;
                __stcs(outp[dd] + i, v);
            }
        }
        return;
    }

    // ---- RIGHT PATH: aligned-LDS shifted, compile-time sub-shift ----
    // Stage plane unswizzled as float4 (conflict-free STS.128).
    #pragma unroll
    for (int p = 0; p < PASSES; ++p) {
        const int i = p * TPB + tid;
        s4[i] = src4[i];
    }
    __syncthreads();

    const int k = dg;                    // float4-granular shift, block-uniform

    #pragma unroll
    for (int p = 0; p < PASSES; ++p) {
        const int i = p * TPB + tid;     // warp = one row (i>>5)
        const int rowbase4 = (i >> 5) << 5;   // row * 32 float4s

        // A covers w-d+j for j>=m; B for j<m. Out-of-range lanes feed only
        // masked slots (lane<k => all masked; lane==k => B slots masked).
        const int ia = lane - k;
        const int ib = lane - k - 1;
        const float4 A = s4[rowbase4 + (ia < 0 ? 0 : ia)];
        const float4 Bv = s4[rowbase4 + (ib < 0 ? 0 : ib)];

        // m = 0: A.x A.y A.z A.w
        {
            const int d = d0 + 0;
            float4 v;
            v.x = (w     >= d) ? A.x : 0.0f;
            v.y = (w + 1 >= d) ? A.y : 0.0f;
            v.z = (w + 2 >= d) ? A.z : 0.0f;
            v.w = (w + 3 >= d) ? A.w : 0.0f;
            __stcs(outp[0] + i, v);
        }
        // m = 1: B.w A.x A.y A.z
        {
            const int d = d0 + 1;
            float4 v;
            v.x = (w     >= d) ? Bv.w : 0.0f;
            v.y = (w + 1 >= d) ? A.x  : 0.0f;
            v.z = (w + 2 >= d) ? A.y  : 0.0f;
            v.w = (w + 3 >= d) ? A.z  : 0.0f;
            __stcs(outp[1] + i, v);
        }
        // m = 2: B.z B.w A.x A.y
        {
            const int d = d0 + 2;
            float4 v;
            v.x = (w     >= d) ? Bv.z : 0.0f;
            v.y = (w + 1 >= d) ? Bv.w : 0.0f;
            v.z = (w + 2 >= d) ? A.x  : 0.0f;
            v.w = (w + 3 >= d) ? A.y  : 0.0f;
            __stcs(outp[2] + i, v);
        }
        // m = 3: B.y B.z B.w A.x
        {
            const int d = d0 + 3;
            float4 v;
            v.x = (w     >= d) ? Bv.y : 0.0f;
            v.y = (w + 1 >= d) ? Bv.z : 0.0f;
            v.z = (w + 2 >= d) ? Bv.w : 0.0f;
            v.w = (w + 3 >= d) ? A.x  : 0.0f;
            __stcs(outp[3] + i, v);
        }
    }
}

extern "C" void kernel_launch(void* const* d_in, const int* in_sizes, int n_in,
                              void* d_out, int out_size)
{
    const float* left  = (const float*)d_in[0];
    const float* right = (const float*)d_in[1];
    float* out = (float*)d_out;

    const int grid = (2 * B * C) * NDG;   // 256 planes * 12 d-groups = 3072
    cost_builder_kernel<<<grid, TPB>>>(left, right, out);
}